// round 1
// baseline (speedup 1.0000x reference)
#include <cuda_runtime.h>
#include <math.h>

#define Bq 512
#define Tq 512
#define Fq 52
#define Eq 64
#define Hq 128
#define G4q 512
#define NROWS (Bq*Tq)

// Scratch (device globals; no dynamic allocation allowed)
__device__ float g_henc[NROWS * Eq];          // 64 MB  [row][64]
__device__ float g_gx[NROWS * G4q];           // 512 MB [t][b][512]
__device__ float g_h[2][Bq * Hq];             // double-buffered hidden state
__device__ float g_c[Bq * Hq];                // cell state

// ---------------------------------------------------------------------------
// zero init of LSTM state
// ---------------------------------------------------------------------------
__global__ void zero_state_kernel() {
    int i = blockIdx.x * blockDim.x + threadIdx.x;
    if (i < Bq * Hq) {
        g_h[0][i] = 0.f;
        g_c[i] = 0.f;
    }
}

// ---------------------------------------------------------------------------
// Fused encoder: h_enc = relu(relu(x @ W1^T + b1) @ W2^T + b2)
// 64-row tiles, 256 threads.
// smem floats: xs 64*53 | w1t 52*128 | h1s 64*128 | w2t 128*64 | b1s 128 | b2s 64
// ---------------------------------------------------------------------------
#define ENC_SMEM_FLOATS (64*53 + 52*128 + 64*128 + 128*64 + 128 + 64)

__global__ __launch_bounds__(256) void enc_kernel(
    const float* __restrict__ x,
    const float* __restrict__ W1, const float* __restrict__ b1,
    const float* __restrict__ W2, const float* __restrict__ b2)
{
    extern __shared__ float sm[];
    float* xs  = sm;                 // [64][53]
    float* w1t = xs  + 64*53;        // [52][128]  w1t[k][c]
    float* h1s = w1t + 52*128;       // [64][128]
    float* w2t = h1s + 64*128;       // [128][64]  w2t[k][e]
    float* b1s = w2t + 128*64;
    float* b2s = b1s + 128;

    const int tid = threadIdx.x;
    const int row0 = blockIdx.x * 64;

    // stage weights (transposed) and x tile
    for (int idx = tid; idx < 128*52; idx += 256) {
        int c = idx / 52, k = idx % 52;
        w1t[k*128 + c] = W1[idx];
    }
    for (int idx = tid; idx < 64*128; idx += 256) {
        int e = idx / 128, k = idx % 128;
        w2t[k*64 + e] = W2[idx];
    }
    if (tid < 128) b1s[tid] = b1[tid];
    if (tid < 64)  b2s[tid] = b2[tid];
    for (int idx = tid; idx < 64*52; idx += 256) {
        int r = idx / 52, k = idx % 52;
        xs[r*53 + k] = x[(size_t)(row0 + r) * Fq + k];
    }
    __syncthreads();

    // ---- layer 1: [64 x 128], K=52 ----
    {
        const int cg = tid & 15, rg = tid >> 4;
        const int c0 = cg * 8, r0 = rg * 4;
        float acc[4][8];
        #pragma unroll
        for (int i = 0; i < 4; i++)
            #pragma unroll
            for (int j = 0; j < 8; j++) acc[i][j] = 0.f;

        #pragma unroll 4
        for (int k = 0; k < Fq; k++) {
            float4 wa = *(const float4*)(w1t + k*128 + c0);
            float4 wb = *(const float4*)(w1t + k*128 + c0 + 4);
            #pragma unroll
            for (int i = 0; i < 4; i++) {
                float xv = xs[(r0 + i)*53 + k];
                acc[i][0] += xv * wa.x; acc[i][1] += xv * wa.y;
                acc[i][2] += xv * wa.z; acc[i][3] += xv * wa.w;
                acc[i][4] += xv * wb.x; acc[i][5] += xv * wb.y;
                acc[i][6] += xv * wb.z; acc[i][7] += xv * wb.w;
            }
        }
        #pragma unroll
        for (int i = 0; i < 4; i++)
            #pragma unroll
            for (int j = 0; j < 8; j++) {
                float v = acc[i][j] + b1s[c0 + j];
                h1s[(r0 + i)*128 + c0 + j] = v > 0.f ? v : 0.f;
            }
    }
    __syncthreads();

    // ---- layer 2: [64 x 64], K=128 ----
    {
        const int cg = tid & 15, rg = tid >> 4;
        const int c0 = cg * 4, r0 = rg * 4;
        float acc[4][4];
        #pragma unroll
        for (int i = 0; i < 4; i++)
            #pragma unroll
            for (int j = 0; j < 4; j++) acc[i][j] = 0.f;

        #pragma unroll 4
        for (int k = 0; k < Hq; k++) {
            float4 w = *(const float4*)(w2t + k*64 + c0);
            #pragma unroll
            for (int i = 0; i < 4; i++) {
                float xv = h1s[(r0 + i)*128 + k];
                acc[i][0] += xv * w.x; acc[i][1] += xv * w.y;
                acc[i][2] += xv * w.z; acc[i][3] += xv * w.w;
            }
        }
        #pragma unroll
        for (int i = 0; i < 4; i++) {
            float4 o;
            float v0 = acc[i][0] + b2s[c0+0]; o.x = v0 > 0.f ? v0 : 0.f;
            float v1 = acc[i][1] + b2s[c0+1]; o.y = v1 > 0.f ? v1 : 0.f;
            float v2 = acc[i][2] + b2s[c0+2]; o.z = v2 > 0.f ? v2 : 0.f;
            float v3 = acc[i][3] + b2s[c0+3]; o.w = v3 > 0.f ? v3 : 0.f;
            *(float4*)(g_henc + (size_t)(row0 + r0 + i) * Eq + c0) = o;
        }
    }
}

// ---------------------------------------------------------------------------
// gx = h_enc @ W_ih^T + (b_ih + b_hh), written as gx[t][b][512]
// grid (4096 row-tiles, 4 col-tiles of 128), 256 threads
// ---------------------------------------------------------------------------
#define GX_SMEM_FLOATS (64*64 + 64*128)

__global__ __launch_bounds__(256) void gx_kernel(
    const float* __restrict__ Wih,
    const float* __restrict__ bih, const float* __restrict__ bhh)
{
    extern __shared__ float sm[];
    float* hes = sm;            // [64][64]
    float* wt  = hes + 64*64;   // [64][128]  wt[k][c]

    const int tid = threadIdx.x;
    const int row0 = blockIdx.x * 64;
    const int cbase = blockIdx.y * 128;

    for (int idx = tid; idx < 64*64/4; idx += 256)
        ((float4*)hes)[idx] = ((const float4*)(g_henc + (size_t)row0 * Eq))[idx];
    for (int idx = tid; idx < 128*64; idx += 256) {
        int c = idx / 64, k = idx % 64;
        wt[k*128 + c] = Wih[(size_t)(cbase + c) * Eq + k];
    }
    __syncthreads();

    const int cg = tid & 15, rg = tid >> 4;
    const int c0 = cg * 8, r0 = rg * 4;
    float acc[4][8];
    #pragma unroll
    for (int i = 0; i < 4; i++)
        #pragma unroll
        for (int j = 0; j < 8; j++) acc[i][j] = 0.f;

    #pragma unroll 4
    for (int k = 0; k < Eq; k++) {
        float4 wa = *(const float4*)(wt + k*128 + c0);
        float4 wb = *(const float4*)(wt + k*128 + c0 + 4);
        #pragma unroll
        for (int i = 0; i < 4; i++) {
            float xv = hes[(r0 + i)*64 + k];
            acc[i][0] += xv * wa.x; acc[i][1] += xv * wa.y;
            acc[i][2] += xv * wa.z; acc[i][3] += xv * wa.w;
            acc[i][4] += xv * wb.x; acc[i][5] += xv * wb.y;
            acc[i][6] += xv * wb.z; acc[i][7] += xv * wb.w;
        }
    }

    #pragma unroll
    for (int i = 0; i < 4; i++) {
        int row = row0 + r0 + i;
        int b = row / Tq, t = row % Tq;
        size_t base = ((size_t)t * Bq + b) * G4q + cbase + c0;
        float4 oa, ob;
        oa.x = acc[i][0] + bih[cbase+c0+0] + bhh[cbase+c0+0];
        oa.y = acc[i][1] + bih[cbase+c0+1] + bhh[cbase+c0+1];
        oa.z = acc[i][2] + bih[cbase+c0+2] + bhh[cbase+c0+2];
        oa.w = acc[i][3] + bih[cbase+c0+3] + bhh[cbase+c0+3];
        ob.x = acc[i][4] + bih[cbase+c0+4] + bhh[cbase+c0+4];
        ob.y = acc[i][5] + bih[cbase+c0+5] + bhh[cbase+c0+5];
        ob.z = acc[i][6] + bih[cbase+c0+6] + bhh[cbase+c0+6];
        ob.w = acc[i][7] + bih[cbase+c0+7] + bhh[cbase+c0+7];
        *(float4*)(g_gx + base)     = oa;
        *(float4*)(g_gx + base + 4) = ob;
    }
}

// ---------------------------------------------------------------------------
// One LSTM timestep, fused GEMM + gate pointwise.
// grid (16 batch-tiles of 32, 8 j-tiles of 16), 256 threads.
// Each CTA owns all 4 gates for its j-slice so it can update c/h locally.
// h double-buffered across steps (read t&1, write (t+1)&1).
// ---------------------------------------------------------------------------
#define WPAD 132
#define L_SMEM_FLOATS (32*128 + 4*16*WPAD)

__global__ __launch_bounds__(256) void lstm_step_kernel(
    const float* __restrict__ Whh, int t)
{
    extern __shared__ float sm[];
    float* hs = sm;               // [32][128]
    float* ws = hs + 32*128;      // [4*16][WPAD]

    const int tid = threadIdx.x;
    const int b0 = blockIdx.x * 32;
    const int j0 = blockIdx.y * 16;
    const float* hin = g_h[t & 1];
    float* hout = g_h[(t + 1) & 1];

    for (int idx = tid; idx < 32*128/4; idx += 256)
        ((float4*)hs)[idx] = ((const float4*)(hin + b0 * Hq))[idx];
    for (int idx = tid; idx < 4*16*128; idx += 256) {
        int q  = idx >> 11;
        int jj = (idx >> 7) & 15;
        int k  = idx & 127;
        ws[(q*16 + jj)*WPAD + k] = Whh[((q << 7) + j0 + jj) * Hq + k];
    }
    __syncthreads();

    const int jj = tid & 15;
    const int bg = tid >> 4;      // 0..15
    const int bl0 = bg * 2;

    float acc[2][4];
    #pragma unroll
    for (int i = 0; i < 2; i++)
        #pragma unroll
        for (int q = 0; q < 4; q++) acc[i][q] = 0.f;

    const float* w0 = ws + (0*16 + jj)*WPAD;
    const float* w1 = ws + (1*16 + jj)*WPAD;
    const float* w2 = ws + (2*16 + jj)*WPAD;
    const float* w3 = ws + (3*16 + jj)*WPAD;

    #pragma unroll 4
    for (int k = 0; k < Hq; k += 4) {
        float4 h0 = *(const float4*)(hs + bl0*128 + k);
        float4 h1 = *(const float4*)(hs + (bl0+1)*128 + k);
        float4 a = *(const float4*)(w0 + k);
        float4 b = *(const float4*)(w1 + k);
        float4 c = *(const float4*)(w2 + k);
        float4 d = *(const float4*)(w3 + k);
        acc[0][0] += h0.x*a.x + h0.y*a.y + h0.z*a.z + h0.w*a.w;
        acc[0][1] += h0.x*b.x + h0.y*b.y + h0.z*b.z + h0.w*b.w;
        acc[0][2] += h0.x*c.x + h0.y*c.y + h0.z*c.z + h0.w*c.w;
        acc[0][3] += h0.x*d.x + h0.y*d.y + h0.z*d.z + h0.w*d.w;
        acc[1][0] += h1.x*a.x + h1.y*a.y + h1.z*a.z + h1.w*a.w;
        acc[1][1] += h1.x*b.x + h1.y*b.y + h1.z*b.z + h1.w*b.w;
        acc[1][2] += h1.x*c.x + h1.y*c.y + h1.z*c.z + h1.w*c.w;
        acc[1][3] += h1.x*d.x + h1.y*d.y + h1.z*d.z + h1.w*d.w;
    }

    #pragma unroll
    for (int bl = 0; bl < 2; bl++) {
        int b = b0 + bl0 + bl;
        int j = j0 + jj;
        size_t gxbase = ((size_t)t * Bq + b) * G4q;
        float vi = acc[bl][0] + g_gx[gxbase + 0*Hq + j];
        float vf = acc[bl][1] + g_gx[gxbase + 1*Hq + j];
        float vg = acc[bl][2] + g_gx[gxbase + 2*Hq + j];
        float vo = acc[bl][3] + g_gx[gxbase + 3*Hq + j];
        float si = 1.f / (1.f + expf(-vi));
        float sf = 1.f / (1.f + expf(-vf));
        float so = 1.f / (1.f + expf(-vo));
        float tg = tanhf(vg);
        float cn = sf * g_c[b*Hq + j] + si * tg;
        g_c[b*Hq + j] = cn;
        hout[b*Hq + j] = so * tanhf(cn);
    }
}

// ---------------------------------------------------------------------------
// Classifier: out = h_final @ Wc^T + bc, [512 x 21], K=128
// ---------------------------------------------------------------------------
__global__ void cls_kernel(const float* __restrict__ Wc,
                           const float* __restrict__ bc,
                           float* __restrict__ out)
{
    int gid = blockIdx.x * blockDim.x + threadIdx.x;
    if (gid >= Bq * 21) return;
    int b = gid / 21, c = gid % 21;
    const float* h = g_h[0] + b * Hq;   // after T=512 (even) steps, final h is in buffer 0
    const float* w = Wc + c * Hq;
    float s = 0.f;
    #pragma unroll 8
    for (int k = 0; k < Hq; k++) s += h[k] * w[k];
    out[gid] = s + bc[c];
}

// ---------------------------------------------------------------------------
extern "C" void kernel_launch(void* const* d_in, const int* in_sizes, int n_in,
                              void* d_out, int out_size)
{
    (void)in_sizes; (void)n_in; (void)out_size;
    const float* x   = (const float*)d_in[0];
    const float* W1  = (const float*)d_in[1];
    const float* b1  = (const float*)d_in[2];
    const float* W2  = (const float*)d_in[3];
    const float* b2  = (const float*)d_in[4];
    const float* Wih = (const float*)d_in[5];
    const float* Whh = (const float*)d_in[6];
    const float* bih = (const float*)d_in[7];
    const float* bhh = (const float*)d_in[8];
    const float* Wc  = (const float*)d_in[9];
    const float* bc  = (const float*)d_in[10];
    float* out = (float*)d_out;

    cudaFuncSetAttribute(enc_kernel, cudaFuncAttributeMaxDynamicSharedMemorySize,
                         ENC_SMEM_FLOATS * (int)sizeof(float));
    cudaFuncSetAttribute(gx_kernel, cudaFuncAttributeMaxDynamicSharedMemorySize,
                         GX_SMEM_FLOATS * (int)sizeof(float));
    cudaFuncSetAttribute(lstm_step_kernel, cudaFuncAttributeMaxDynamicSharedMemorySize,
                         L_SMEM_FLOATS * (int)sizeof(float));

    zero_state_kernel<<<(Bq*Hq + 255)/256, 256>>>();

    enc_kernel<<<NROWS/64, 256, ENC_SMEM_FLOATS * sizeof(float)>>>(x, W1, b1, W2, b2);

    gx_kernel<<<dim3(NROWS/64, 4), 256, GX_SMEM_FLOATS * sizeof(float)>>>(Wih, bih, bhh);

    for (int t = 0; t < Tq; t++)
        lstm_step_kernel<<<dim3(16, 8), 256, L_SMEM_FLOATS * sizeof(float)>>>(Whh, t);

    cls_kernel<<<(Bq*21 + 255)/256, 256>>>(Wc, bc, out);
}

// round 3
// speedup vs baseline: 1.9402x; 1.9402x over previous
#include <cuda_runtime.h>
#include <stdint.h>
#include <math.h>

#define Bq 512
#define Tq 512
#define Fq 52
#define Eq 64
#define Hq 128
#define G4q 512
#define NROWS (Bq*Tq)

// Scratch (device globals; no dynamic allocation allowed)
__device__ float g_henc[NROWS * Eq];          // 64 MB  [row][64]
__device__ float g_gx[NROWS * G4q];           // 512 MB [t][b][512]
__device__ float g_hfin[Bq * Hq];             // final hidden state

// ---------------------------------------------------------------------------
// helpers
// ---------------------------------------------------------------------------
__device__ __forceinline__ unsigned smem_u32(const void* p) {
    unsigned a;
    asm("{ .reg .u64 t; cvta.to.shared.u64 t, %1; cvt.u32.u64 %0, t; }"
        : "=r"(a) : "l"(p));
    return a;
}

__device__ __forceinline__ float sigf(float x) {
    // safe: exp overflow -> inf -> 1/(1+inf)=0 (correct limit)
    return __fdividef(1.f, 1.f + __expf(-x));
}
__device__ __forceinline__ float tanhf_s(float x) {
    float ax = fabsf(x);
    float e  = __expf(-2.f * ax);            // in (0,1], never overflows
    float r  = __fdividef(1.f - e, 1.f + e);
    return copysignf(r, x);
}

// ---------------------------------------------------------------------------
// Fused encoder: h_enc = relu(relu(x @ W1^T + b1) @ W2^T + b2)
// ---------------------------------------------------------------------------
#define ENC_SMEM_FLOATS (64*53 + 52*128 + 64*128 + 128*64 + 128 + 64)

__global__ __launch_bounds__(256) void enc_kernel(
    const float* __restrict__ x,
    const float* __restrict__ W1, const float* __restrict__ b1,
    const float* __restrict__ W2, const float* __restrict__ b2)
{
    extern __shared__ float sm[];
    float* xs  = sm;                 // [64][53]
    float* w1t = xs  + 64*53;        // [52][128]
    float* h1s = w1t + 52*128;       // [64][128]
    float* w2t = h1s + 64*128;       // [128][64]
    float* b1s = w2t + 128*64;
    float* b2s = b1s + 128;

    const int tid = threadIdx.x;
    const int row0 = blockIdx.x * 64;

    for (int idx = tid; idx < 128*52; idx += 256) {
        int c = idx / 52, k = idx % 52;
        w1t[k*128 + c] = W1[idx];
    }
    for (int idx = tid; idx < 64*128; idx += 256) {
        int e = idx / 128, k = idx % 128;
        w2t[k*64 + e] = W2[idx];
    }
    if (tid < 128) b1s[tid] = b1[tid];
    if (tid < 64)  b2s[tid] = b2[tid];
    for (int idx = tid; idx < 64*52; idx += 256) {
        int r = idx / 52, k = idx % 52;
        xs[r*53 + k] = x[(size_t)(row0 + r) * Fq + k];
    }
    __syncthreads();

    // layer 1
    {
        const int cg = tid & 15, rg = tid >> 4;
        const int c0 = cg * 8, r0 = rg * 4;
        float acc[4][8];
        #pragma unroll
        for (int i = 0; i < 4; i++)
            #pragma unroll
            for (int j = 0; j < 8; j++) acc[i][j] = 0.f;

        #pragma unroll 4
        for (int k = 0; k < Fq; k++) {
            float4 wa = *(const float4*)(w1t + k*128 + c0);
            float4 wb = *(const float4*)(w1t + k*128 + c0 + 4);
            #pragma unroll
            for (int i = 0; i < 4; i++) {
                float xv = xs[(r0 + i)*53 + k];
                acc[i][0] += xv * wa.x; acc[i][1] += xv * wa.y;
                acc[i][2] += xv * wa.z; acc[i][3] += xv * wa.w;
                acc[i][4] += xv * wb.x; acc[i][5] += xv * wb.y;
                acc[i][6] += xv * wb.z; acc[i][7] += xv * wb.w;
            }
        }
        #pragma unroll
        for (int i = 0; i < 4; i++)
            #pragma unroll
            for (int j = 0; j < 8; j++) {
                float v = acc[i][j] + b1s[c0 + j];
                h1s[(r0 + i)*128 + c0 + j] = v > 0.f ? v : 0.f;
            }
    }
    __syncthreads();

    // layer 2
    {
        const int cg = tid & 15, rg = tid >> 4;
        const int c0 = cg * 4, r0 = rg * 4;
        float acc[4][4];
        #pragma unroll
        for (int i = 0; i < 4; i++)
            #pragma unroll
            for (int j = 0; j < 4; j++) acc[i][j] = 0.f;

        #pragma unroll 4
        for (int k = 0; k < Hq; k++) {
            float4 w = *(const float4*)(w2t + k*64 + c0);
            #pragma unroll
            for (int i = 0; i < 4; i++) {
                float xv = h1s[(r0 + i)*128 + k];
                acc[i][0] += xv * w.x; acc[i][1] += xv * w.y;
                acc[i][2] += xv * w.z; acc[i][3] += xv * w.w;
            }
        }
        #pragma unroll
        for (int i = 0; i < 4; i++) {
            float4 o;
            float v0 = acc[i][0] + b2s[c0+0]; o.x = v0 > 0.f ? v0 : 0.f;
            float v1 = acc[i][1] + b2s[c0+1]; o.y = v1 > 0.f ? v1 : 0.f;
            float v2 = acc[i][2] + b2s[c0+2]; o.z = v2 > 0.f ? v2 : 0.f;
            float v3 = acc[i][3] + b2s[c0+3]; o.w = v3 > 0.f ? v3 : 0.f;
            *(float4*)(g_henc + (size_t)(row0 + r0 + i) * Eq + c0) = o;
        }
    }
}

// ---------------------------------------------------------------------------
// gx = h_enc @ W_ih^T + (b_ih + b_hh), written as gx[t][b][512]
// ---------------------------------------------------------------------------
#define GX_SMEM_FLOATS (64*64 + 64*128)

__global__ __launch_bounds__(256) void gx_kernel(
    const float* __restrict__ Wih,
    const float* __restrict__ bih, const float* __restrict__ bhh)
{
    extern __shared__ float sm[];
    float* hes = sm;            // [64][64]
    float* wt  = hes + 64*64;   // [64][128]

    const int tid = threadIdx.x;
    const int row0 = blockIdx.x * 64;
    const int cbase = blockIdx.y * 128;

    for (int idx = tid; idx < 64*64/4; idx += 256)
        ((float4*)hes)[idx] = ((const float4*)(g_henc + (size_t)row0 * Eq))[idx];
    for (int idx = tid; idx < 128*64; idx += 256) {
        int c = idx / 64, k = idx % 64;
        wt[k*128 + c] = Wih[(size_t)(cbase + c) * Eq + k];
    }
    __syncthreads();

    const int cg = tid & 15, rg = tid >> 4;
    const int c0 = cg * 8, r0 = rg * 4;
    float acc[4][8];
    #pragma unroll
    for (int i = 0; i < 4; i++)
        #pragma unroll
        for (int j = 0; j < 8; j++) acc[i][j] = 0.f;

    #pragma unroll 4
    for (int k = 0; k < Eq; k++) {
        float4 wa = *(const float4*)(wt + k*128 + c0);
        float4 wb = *(const float4*)(wt + k*128 + c0 + 4);
        #pragma unroll
        for (int i = 0; i < 4; i++) {
            float xv = hes[(r0 + i)*64 + k];
            acc[i][0] += xv * wa.x; acc[i][1] += xv * wa.y;
            acc[i][2] += xv * wa.z; acc[i][3] += xv * wa.w;
            acc[i][4] += xv * wb.x; acc[i][5] += xv * wb.y;
            acc[i][6] += xv * wb.z; acc[i][7] += xv * wb.w;
        }
    }

    #pragma unroll
    for (int i = 0; i < 4; i++) {
        int row = row0 + r0 + i;
        int b = row / Tq, t = row % Tq;
        size_t base = ((size_t)t * Bq + b) * G4q + cbase + c0;
        float4 oa, ob;
        oa.x = acc[i][0] + bih[cbase+c0+0] + bhh[cbase+c0+0];
        oa.y = acc[i][1] + bih[cbase+c0+1] + bhh[cbase+c0+1];
        oa.z = acc[i][2] + bih[cbase+c0+2] + bhh[cbase+c0+2];
        oa.w = acc[i][3] + bih[cbase+c0+3] + bhh[cbase+c0+3];
        ob.x = acc[i][4] + bih[cbase+c0+4] + bhh[cbase+c0+4];
        ob.y = acc[i][5] + bih[cbase+c0+5] + bhh[cbase+c0+5];
        ob.z = acc[i][6] + bih[cbase+c0+6] + bhh[cbase+c0+6];
        ob.w = acc[i][7] + bih[cbase+c0+7] + bhh[cbase+c0+7];
        *(float4*)(g_gx + base)     = oa;
        *(float4*)(g_gx + base + 4) = ob;
    }
}

// ---------------------------------------------------------------------------
// Persistent LSTM: one kernel for all 512 timesteps.
// 64 clusters x 2 CTAs, 256 threads. Cluster cl owns batches [cl*8, cl*8+8).
// CTA rank r owns gate columns j in [r*64, r*64+64) (all 4 gates).
// W_hh half (128 KB) stays smem-resident for the whole kernel.
// Per step: GEMM (8 b x 256 gates x K=128) -> gates -> c,h update ->
//           write h-half to self + peer smem (DSMEM) -> barrier.cluster.
// ---------------------------------------------------------------------------
#define L_HS_FLOATS  (2*8*128)           // ping-pong h buffers
#define L_WS_FLOATS  (128*64*4)          // w[k][jl][g]
#define L_SMEM_FLOATS (L_HS_FLOATS + L_WS_FLOATS)

__global__ __launch_bounds__(256, 1) __cluster_dims__(2, 1, 1)
void lstm_persist_kernel(const float* __restrict__ Whh)
{
    extern __shared__ float sm[];
    float* hs = sm;                  // [2][8][128]
    float* ws = sm + L_HS_FLOATS;    // [128][64][4]

    const int tid = threadIdx.x;
    unsigned rank;
    asm("mov.u32 %0, %%cluster_ctarank;" : "=r"(rank));
    const int cl = blockIdx.x >> 1;          // cluster id 0..63
    const int j0 = (int)rank * 64;           // my j-half base

    // Stage weights once: ws[k][jl][g] = Whh[(g*128 + j0 + jl)*128 + k]
    for (int idx = tid; idx < L_WS_FLOATS; idx += 256) {
        int g  = idx & 3;
        int jl = (idx >> 2) & 63;
        int k  = idx >> 8;
        ws[idx] = Whh[((g << 7) + j0 + jl) * Hq + k];
    }
    // Zero both h buffers
    for (int idx = tid; idx < L_HS_FLOATS; idx += 256) hs[idx] = 0.f;
    __syncthreads();
    // ensure peer won't DSMEM-write into my buffers before init done
    asm volatile("barrier.cluster.arrive.aligned;" ::: "memory");
    asm volatile("barrier.cluster.wait.aligned;" ::: "memory");

    // thread mapping
    const int jj  = tid & 63;       // local j 0..63 (lanes consecutive)
    const int bg  = tid >> 6;       // 0..3
    const int bl0 = bg * 2;         // two local batches bl0, bl0+1
    const int jglob = j0 + jj;

    // peer smem base for hs
    unsigned hs_loc = smem_u32(hs);
    unsigned hs_peer;
    asm("mapa.shared::cluster.u32 %0, %1, %2;"
        : "=r"(hs_peer) : "r"(hs_loc), "r"(rank ^ 1u));

    const float4* wsv = (const float4*)ws;   // element k*64+jl = {g0,g1,g2,g3}

    float creg[2] = {0.f, 0.f};
    int p = 0;

    const size_t gx_stride_t = (size_t)Bq * G4q;
    const float* gx_b0 = g_gx + (size_t)(cl * 8 + bl0) * G4q + jglob;

    for (int t = 0; t < Tq; t++) {
        // prefetch gx for this step (consumed only in epilogue)
        const float* gxp = gx_b0 + (size_t)t * gx_stride_t;
        float gxr[2][4];
        #pragma unroll
        for (int g = 0; g < 4; g++) {
            gxr[0][g] = __ldg(gxp + g * Hq);
            gxr[1][g] = __ldg(gxp + G4q + g * Hq);
        }

        // GEMM: acc[b][g] = sum_k h[b][k] * Whh[g*128+jglob][k]
        float acc[2][4];
        #pragma unroll
        for (int b = 0; b < 2; b++)
            #pragma unroll
            for (int g = 0; g < 4; g++) acc[b][g] = 0.f;

        const float4* hb0 = (const float4*)(hs + p * 1024 + bl0 * 128);
        const float4* hb1 = (const float4*)(hs + p * 1024 + (bl0 + 1) * 128);

        #pragma unroll 8
        for (int k4 = 0; k4 < 32; k4++) {
            float4 h0 = hb0[k4];
            float4 h1 = hb1[k4];
            const float4* wk = wsv + (k4 * 4) * 64 + jj;
            float4 w0 = wk[0];
            float4 w1 = wk[64];
            float4 w2 = wk[128];
            float4 w3 = wk[192];
            acc[0][0] = fmaf(h0.x, w0.x, acc[0][0]);
            acc[0][1] = fmaf(h0.x, w0.y, acc[0][1]);
            acc[0][2] = fmaf(h0.x, w0.z, acc[0][2]);
            acc[0][3] = fmaf(h0.x, w0.w, acc[0][3]);
            acc[1][0] = fmaf(h1.x, w0.x, acc[1][0]);
            acc[1][1] = fmaf(h1.x, w0.y, acc[1][1]);
            acc[1][2] = fmaf(h1.x, w0.z, acc[1][2]);
            acc[1][3] = fmaf(h1.x, w0.w, acc[1][3]);

            acc[0][0] = fmaf(h0.y, w1.x, acc[0][0]);
            acc[0][1] = fmaf(h0.y, w1.y, acc[0][1]);
            acc[0][2] = fmaf(h0.y, w1.z, acc[0][2]);
            acc[0][3] = fmaf(h0.y, w1.w, acc[0][3]);
            acc[1][0] = fmaf(h1.y, w1.x, acc[1][0]);
            acc[1][1] = fmaf(h1.y, w1.y, acc[1][1]);
            acc[1][2] = fmaf(h1.y, w1.z, acc[1][2]);
            acc[1][3] = fmaf(h1.y, w1.w, acc[1][3]);

            acc[0][0] = fmaf(h0.z, w2.x, acc[0][0]);
            acc[0][1] = fmaf(h0.z, w2.y, acc[0][1]);
            acc[0][2] = fmaf(h0.z, w2.z, acc[0][2]);
            acc[0][3] = fmaf(h0.z, w2.w, acc[0][3]);
            acc[1][0] = fmaf(h1.z, w2.x, acc[1][0]);
            acc[1][1] = fmaf(h1.z, w2.y, acc[1][1]);
            acc[1][2] = fmaf(h1.z, w2.z, acc[1][2]);
            acc[1][3] = fmaf(h1.z, w2.w, acc[1][3]);

            acc[0][0] = fmaf(h0.w, w3.x, acc[0][0]);
            acc[0][1] = fmaf(h0.w, w3.y, acc[0][1]);
            acc[0][2] = fmaf(h0.w, w3.z, acc[0][2]);
            acc[0][3] = fmaf(h0.w, w3.w, acc[0][3]);
            acc[1][0] = fmaf(h1.w, w3.x, acc[1][0]);
            acc[1][1] = fmaf(h1.w, w3.y, acc[1][1]);
            acc[1][2] = fmaf(h1.w, w3.z, acc[1][2]);
            acc[1][3] = fmaf(h1.w, w3.w, acc[1][3]);
        }

        // gates + state update + h write (self + peer)
        const int pw = p ^ 1;
        #pragma unroll
        for (int b = 0; b < 2; b++) {
            float vi = acc[b][0] + gxr[b][0];
            float vf = acc[b][1] + gxr[b][1];
            float vg = acc[b][2] + gxr[b][2];
            float vo = acc[b][3] + gxr[b][3];
            float si = sigf(vi);
            float sf = sigf(vf);
            float so = sigf(vo);
            float tg = tanhf_s(vg);
            float cn = sf * creg[b] + si * tg;
            creg[b] = cn;
            float hn = so * tanhf_s(cn);
            int off = pw * 1024 + (bl0 + b) * 128 + jglob;
            hs[off] = hn;
            asm volatile("st.shared::cluster.f32 [%0], %1;"
                         :: "r"(hs_peer + (unsigned)off * 4u), "f"(hn)
                         : "memory");
        }

        // step barrier: orders my h writes (incl. DSMEM) before peer's reads
        asm volatile("barrier.cluster.arrive.aligned;" ::: "memory");
        asm volatile("barrier.cluster.wait.aligned;" ::: "memory");
        p ^= 1;
    }

    // final h is in hs[0] (512 steps, even). rank 0 publishes to global.
    if (rank == 0) {
        float* dst = g_hfin + (size_t)(cl * 8) * Hq;
        for (int idx = tid; idx < 8 * 128; idx += 256)
            dst[idx] = hs[idx];
    }
}

// ---------------------------------------------------------------------------
// Classifier: out = h_final @ Wc^T + bc, [512 x 21], K=128
// ---------------------------------------------------------------------------
__global__ void cls_kernel(const float* __restrict__ Wc,
                           const float* __restrict__ bc,
                           float* __restrict__ out)
{
    int gid = blockIdx.x * blockDim.x + threadIdx.x;
    if (gid >= Bq * 21) return;
    int b = gid / 21, c = gid % 21;
    const float* h = g_hfin + b * Hq;
    const float* w = Wc + c * Hq;
    float s = 0.f;
    #pragma unroll 8
    for (int k = 0; k < Hq; k++) s += h[k] * w[k];
    out[gid] = s + bc[c];
}

// ---------------------------------------------------------------------------
extern "C" void kernel_launch(void* const* d_in, const int* in_sizes, int n_in,
                              void* d_out, int out_size)
{
    (void)in_sizes; (void)n_in; (void)out_size;
    const float* x   = (const float*)d_in[0];
    const float* W1  = (const float*)d_in[1];
    const float* b1  = (const float*)d_in[2];
    const float* W2  = (const float*)d_in[3];
    const float* b2  = (const float*)d_in[4];
    const float* Wih = (const float*)d_in[5];
    const float* Whh = (const float*)d_in[6];
    const float* bih = (const float*)d_in[7];
    const float* bhh = (const float*)d_in[8];
    const float* Wc  = (const float*)d_in[9];
    const float* bc  = (const float*)d_in[10];
    float* out = (float*)d_out;

    cudaFuncSetAttribute(enc_kernel, cudaFuncAttributeMaxDynamicSharedMemorySize,
                         ENC_SMEM_FLOATS * (int)sizeof(float));
    cudaFuncSetAttribute(gx_kernel, cudaFuncAttributeMaxDynamicSharedMemorySize,
                         GX_SMEM_FLOATS * (int)sizeof(float));
    cudaFuncSetAttribute(lstm_persist_kernel, cudaFuncAttributeMaxDynamicSharedMemorySize,
                         L_SMEM_FLOATS * (int)sizeof(float));

    enc_kernel<<<NROWS/64, 256, ENC_SMEM_FLOATS * sizeof(float)>>>(x, W1, b1, W2, b2);

    gx_kernel<<<dim3(NROWS/64, 4), 256, GX_SMEM_FLOATS * sizeof(float)>>>(Wih, bih, bhh);

    lstm_persist_kernel<<<128, 256, L_SMEM_FLOATS * sizeof(float)>>>(Whh);

    cls_kernel<<<(Bq*21 + 255)/256, 256>>>(Wc, bc, out);
}